// round 3
// baseline (speedup 1.0000x reference)
#include <cuda_runtime.h>
#include <cuda_bf16.h>
#include <cstdint>

#define Bdim 4
#define Hdim 16
#define Ndim 2048
#define Ddim 64
#define TOTE (Bdim*Hdim*Ndim*Ddim)   // 8388608

// bf16 scratch in [B, H, N, D] layout
__device__ __align__(16) __nv_bfloat16 g_q[TOTE];
__device__ __align__(16) __nv_bfloat16 g_k[TOTE];
__device__ __align__(16) __nv_bfloat16 g_v[TOTE];

// ---------------- converter: [B,N,H*D] f32 -> [B,H,N,D] bf16 ----------------
__global__ void cvt_kernel(const float* __restrict__ q,
                           const float* __restrict__ k,
                           const float* __restrict__ v) {
    long i4 = (long)blockIdx.x * blockDim.x + threadIdx.x;
    long o = i4 * 4;                      // output linear index (d fastest)
    if (o >= TOTE) return;
    int d = (int)(o & 63);
    int n = (int)((o >> 6) & 2047);
    int h = (int)((o >> 17) & 15);
    int b = (int)(o >> 21);
    long in_off = (((long)b * Ndim + n) * Hdim + h) * Ddim + d;

    float4 fq = *(const float4*)(q + in_off);
    float4 fk = *(const float4*)(k + in_off);
    float4 fv = *(const float4*)(v + in_off);

    __nv_bfloat162 q0 = __floats2bfloat162_rn(fq.x, fq.y);
    __nv_bfloat162 q1 = __floats2bfloat162_rn(fq.z, fq.w);
    __nv_bfloat162 k0 = __floats2bfloat162_rn(fk.x, fk.y);
    __nv_bfloat162 k1 = __floats2bfloat162_rn(fk.z, fk.w);
    __nv_bfloat162 v0 = __floats2bfloat162_rn(fv.x, fv.y);
    __nv_bfloat162 v1 = __floats2bfloat162_rn(fv.z, fv.w);

    uint2 uq = { *(uint32_t*)&q0, *(uint32_t*)&q1 };
    uint2 uk = { *(uint32_t*)&k0, *(uint32_t*)&k1 };
    uint2 uv = { *(uint32_t*)&v0, *(uint32_t*)&v1 };
    *(uint2*)(g_q + o) = uq;
    *(uint2*)(g_k + o) = uk;
    *(uint2*)(g_v + o) = uv;
}

// ---------------- helpers ----------------
__device__ __forceinline__ unsigned su(const void* p) {
    return (unsigned)__cvta_generic_to_shared(p);
}
__device__ __forceinline__ void ldsm_x4(uint32_t r[4], unsigned addr) {
    asm volatile("ldmatrix.sync.aligned.m8n8.x4.shared.b16 {%0,%1,%2,%3}, [%4];"
                 : "=r"(r[0]), "=r"(r[1]), "=r"(r[2]), "=r"(r[3]) : "r"(addr));
}
__device__ __forceinline__ void ldsm_x4_t(uint32_t r[4], unsigned addr) {
    asm volatile("ldmatrix.sync.aligned.m8n8.x4.trans.shared.b16 {%0,%1,%2,%3}, [%4];"
                 : "=r"(r[0]), "=r"(r[1]), "=r"(r[2]), "=r"(r[3]) : "r"(addr));
}
__device__ __forceinline__ void mma16816(float c[4],
                                         uint32_t a0, uint32_t a1, uint32_t a2, uint32_t a3,
                                         uint32_t b0, uint32_t b1) {
    asm volatile(
        "mma.sync.aligned.m16n8k16.row.col.f32.bf16.bf16.f32 "
        "{%0,%1,%2,%3}, {%4,%5,%6,%7}, {%8,%9}, {%0,%1,%2,%3};"
        : "+f"(c[0]), "+f"(c[1]), "+f"(c[2]), "+f"(c[3])
        : "r"(a0), "r"(a1), "r"(a2), "r"(a3), "r"(b0), "r"(b1));
}
// round f32 -> bf16 -> f32 (match reference's bf16 quantization)
__device__ __forceinline__ float rb(float x) {
    return __bfloat162float(__float2bfloat16(x));
}
__device__ __forceinline__ uint32_t pack_bf2(float a, float b) {
    __nv_bfloat162 t = __floats2bfloat162_rn(a, b);
    return *reinterpret_cast<uint32_t*>(&t);
}

// ---------------- flash attention, two-pass (bf16-rounding-exact) ----------------
// grid: (16 m-tiles, 64 bh); block: 256 threads (8 warps, 16 rows each)
__global__ __launch_bounds__(256, 2) void attn_kernel(float* __restrict__ out) {
    constexpr int SQ = 72;   // smem row stride (bf16 elems)
    __shared__ __align__(16) __nv_bfloat16 sQ[128 * SQ];
    __shared__ __align__(16) __nv_bfloat16 sK[64 * SQ];
    __shared__ __align__(16) __nv_bfloat16 sV[64 * SQ];

    const int tid  = threadIdx.x;
    const int warp = tid >> 5;
    const int lane = tid & 31;
    const int mblk = blockIdx.x;   // 0..15
    const int bh   = blockIdx.y;   // 0..63

    const __nv_bfloat16* Qg = g_q + (size_t)bh * Ndim * Ddim + (size_t)mblk * 128 * Ddim;
    const __nv_bfloat16* Kg = g_k + (size_t)bh * Ndim * Ddim;
    const __nv_bfloat16* Vg = g_v + (size_t)bh * Ndim * Ddim;

    // ---- load Q tile (128x64 bf16) ----
    {
        const uint4* src = (const uint4*)Qg;
        #pragma unroll
        for (int i = tid; i < 128 * 8; i += 256) {
            int row = i >> 3, c = i & 7;
            *(uint4*)&sQ[row * SQ + c * 8] = src[i];
        }
    }
    __syncthreads();

    // ---- Q fragments, register resident ----
    uint32_t qa[4][4];
    {
        int rofs = warp * 16 + (lane & 15);
        int cofs = (lane & 16) ? 8 : 0;
        #pragma unroll
        for (int kk = 0; kk < 4; kk++)
            ldsm_x4(qa[kk], su(&sQ[rofs * SQ + kk * 16 + cofs]));
    }

    const int qgrp = lane >> 2;
    const int krow = lane & 7;
    const int kc8  = (lane >> 3) & 3;
    const int vrow = lane & 15;
    const int vcsel = (lane & 16) ? 8 : 0;

    // ===================== PASS 1: row max m and denom l =====================
    float m0 = -1e30f, m1 = -1e30f, l0 = 0.f, l1 = 0.f;

    for (int kt = 0; kt < 32; kt++) {
        __syncthreads();
        {
            const uint4* srcK = (const uint4*)(Kg + kt * 64 * Ddim);
            #pragma unroll
            for (int i = tid; i < 64 * 8; i += 256) {
                int row = i >> 3, c = i & 7;
                *(uint4*)&sK[row * SQ + c * 8] = srcK[i];
            }
        }
        __syncthreads();

        float sc[8][4];
        #pragma unroll
        for (int nt = 0; nt < 8; nt++)
            #pragma unroll
            for (int x = 0; x < 4; x++) sc[nt][x] = 0.f;

        #pragma unroll
        for (int nt = 0; nt < 8; nt++) {
            #pragma unroll
            for (int kh = 0; kh < 2; kh++) {
                uint32_t kb[4];
                ldsm_x4(kb, su(&sK[(nt * 8 + krow) * SQ + kh * 32 + kc8 * 8]));
                mma16816(sc[nt], qa[2*kh][0], qa[2*kh][1], qa[2*kh][2], qa[2*kh][3], kb[0], kb[1]);
                mma16816(sc[nt], qa[2*kh+1][0], qa[2*kh+1][1], qa[2*kh+1][2], qa[2*kh+1][3], kb[2], kb[3]);
            }
        }

        // round to bf16 like the reference einsum, then exact *0.125
        #pragma unroll
        for (int nt = 0; nt < 8; nt++) {
            sc[nt][0] = 0.125f * rb(sc[nt][0]);
            sc[nt][1] = 0.125f * rb(sc[nt][1]);
            sc[nt][2] = 0.125f * rb(sc[nt][2]);
            sc[nt][3] = 0.125f * rb(sc[nt][3]);
        }

        float mx0 = -1e30f, mx1 = -1e30f;
        #pragma unroll
        for (int nt = 0; nt < 8; nt++) {
            mx0 = fmaxf(mx0, fmaxf(sc[nt][0], sc[nt][1]));
            mx1 = fmaxf(mx1, fmaxf(sc[nt][2], sc[nt][3]));
        }
        mx0 = fmaxf(mx0, __shfl_xor_sync(0xffffffffu, mx0, 1));
        mx0 = fmaxf(mx0, __shfl_xor_sync(0xffffffffu, mx0, 2));
        mx1 = fmaxf(mx1, __shfl_xor_sync(0xffffffffu, mx1, 1));
        mx1 = fmaxf(mx1, __shfl_xor_sync(0xffffffffu, mx1, 2));

        float mn0 = fmaxf(m0, mx0), mn1 = fmaxf(m1, mx1);
        float al0 = expf(m0 - mn0);
        float al1 = expf(m1 - mn1);
        m0 = mn0; m1 = mn1;

        float rs0 = 0.f, rs1 = 0.f;
        #pragma unroll
        for (int nt = 0; nt < 8; nt++) {
            rs0 += expf(sc[nt][0] - m0) + expf(sc[nt][1] - m0);
            rs1 += expf(sc[nt][2] - m1) + expf(sc[nt][3] - m1);
        }
        l0 = l0 * al0 + rs0;   // per-thread partial (its 16 of 64 cols)
        l1 = l1 * al1 + rs1;
    }
    // reduce partials across the 4 lanes of each row group
    l0 += __shfl_xor_sync(0xffffffffu, l0, 1);
    l0 += __shfl_xor_sync(0xffffffffu, l0, 2);
    l1 += __shfl_xor_sync(0xffffffffu, l1, 1);
    l1 += __shfl_xor_sync(0xffffffffu, l1, 2);
    const float invl0 = 1.0f / l0;
    const float invl1 = 1.0f / l1;

    // ===================== PASS 2: P = bf16(exp(s-m)/l), O = P V =====================
    float oa[8][4];
    #pragma unroll
    for (int u = 0; u < 8; u++)
        #pragma unroll
        for (int x = 0; x < 4; x++) oa[u][x] = 0.f;

    for (int kt = 0; kt < 32; kt++) {
        __syncthreads();
        {
            const uint4* srcK = (const uint4*)(Kg + kt * 64 * Ddim);
            const uint4* srcV = (const uint4*)(Vg + kt * 64 * Ddim);
            #pragma unroll
            for (int i = tid; i < 64 * 8; i += 256) {
                int row = i >> 3, c = i & 7;
                *(uint4*)&sK[row * SQ + c * 8] = srcK[i];
                *(uint4*)&sV[row * SQ + c * 8] = srcV[i];
            }
        }
        __syncthreads();

        float sc[8][4];
        #pragma unroll
        for (int nt = 0; nt < 8; nt++)
            #pragma unroll
            for (int x = 0; x < 4; x++) sc[nt][x] = 0.f;

        #pragma unroll
        for (int nt = 0; nt < 8; nt++) {
            #pragma unroll
            for (int kh = 0; kh < 2; kh++) {
                uint32_t kb[4];
                ldsm_x4(kb, su(&sK[(nt * 8 + krow) * SQ + kh * 32 + kc8 * 8]));
                mma16816(sc[nt], qa[2*kh][0], qa[2*kh][1], qa[2*kh][2], qa[2*kh][3], kb[0], kb[1]);
                mma16816(sc[nt], qa[2*kh+1][0], qa[2*kh+1][1], qa[2*kh+1][2], qa[2*kh+1][3], kb[2], kb[3]);
            }
        }

        uint32_t pA[8][2];
        #pragma unroll
        for (int nt = 0; nt < 8; nt++) {
            float s00 = 0.125f * rb(sc[nt][0]);
            float s01 = 0.125f * rb(sc[nt][1]);
            float s10 = 0.125f * rb(sc[nt][2]);
            float s11 = 0.125f * rb(sc[nt][3]);
            float p00 = expf(s00 - m0) * invl0;
            float p01 = expf(s01 - m0) * invl0;
            float p10 = expf(s10 - m1) * invl1;
            float p11 = expf(s11 - m1) * invl1;
            pA[nt][0] = pack_bf2(p00, p01);   // bf16-rounded normalized probs
            pA[nt][1] = pack_bf2(p10, p11);
        }

        #pragma unroll
        for (int j = 0; j < 4; j++) {
            uint32_t A0 = pA[2*j][0], A1 = pA[2*j][1];
            uint32_t A2 = pA[2*j+1][0], A3 = pA[2*j+1][1];
            #pragma unroll
            for (int up = 0; up < 4; up++) {
                uint32_t vb[4];
                ldsm_x4_t(vb, su(&sV[(j * 16 + vrow) * SQ + up * 16 + vcsel]));
                mma16816(oa[2*up],     A0, A1, A2, A3, vb[0], vb[1]);
                mma16816(oa[2*up + 1], A0, A1, A2, A3, vb[2], vb[3]);
            }
        }
    }

    // ---- epilogue: bf16-round O, store as float32 in [B,N,H*D] ----
    int b = bh >> 4, h = bh & 15;
    int n0 = mblk * 128 + warp * 16 + qgrp;
    size_t base0 = ((size_t)b * Ndim + n0) * (Hdim * Ddim) + (size_t)h * Ddim;
    size_t base1 = base0 + (size_t)8 * (Hdim * Ddim);
    const int tq = lane & 3;
    #pragma unroll
    for (int u = 0; u < 8; u++) {
        int d = u * 8 + 2 * tq;
        float2 w0 = { rb(oa[u][0]), rb(oa[u][1]) };
        float2 w1 = { rb(oa[u][2]), rb(oa[u][3]) };
        *(float2*)(out + base0 + d) = w0;
        *(float2*)(out + base1 + d) = w1;
    }
}

// ---------------- launch ----------------
extern "C" void kernel_launch(void* const* d_in, const int* in_sizes, int n_in,
                              void* d_out, int out_size) {
    (void)in_sizes; (void)n_in; (void)out_size;
    const float* q = (const float*)d_in[0];
    const float* k = (const float*)d_in[1];
    const float* v = (const float*)d_in[2];
    float* out = (float*)d_out;

    cvt_kernel<<<TOTE / 1024, 256>>>(q, k, v);

    dim3 grid(Ndim / 128, Bdim * Hdim);
    attn_kernel<<<grid, 256>>>(out);
}

// round 4
// speedup vs baseline: 1.2539x; 1.2539x over previous
#include <cuda_runtime.h>
#include <cuda_bf16.h>
#include <cstdint>

#define Bdim 4
#define Hdim 16
#define Ndim 2048
#define Ddim 64
#define TOTE (Bdim*Hdim*Ndim*Ddim)   // 8388608

// bf16 scratch in [B, H, N, D] layout
__device__ __align__(16) __nv_bfloat16 g_q[TOTE];
__device__ __align__(16) __nv_bfloat16 g_k[TOTE];
__device__ __align__(16) __nv_bfloat16 g_v[TOTE];

// ---------------- converter: [B,N,H*D] f32 -> [B,H,N,D] bf16 ----------------
__global__ void cvt_kernel(const float* __restrict__ q,
                           const float* __restrict__ k,
                           const float* __restrict__ v) {
    long i4 = (long)blockIdx.x * blockDim.x + threadIdx.x;
    long o = i4 * 4;
    if (o >= TOTE) return;
    int d = (int)(o & 63);
    int n = (int)((o >> 6) & 2047);
    int h = (int)((o >> 17) & 15);
    int b = (int)(o >> 21);
    long in_off = (((long)b * Ndim + n) * Hdim + h) * Ddim + d;

    float4 fq = *(const float4*)(q + in_off);
    float4 fk = *(const float4*)(k + in_off);
    float4 fv = *(const float4*)(v + in_off);

    __nv_bfloat162 q0 = __floats2bfloat162_rn(fq.x, fq.y);
    __nv_bfloat162 q1 = __floats2bfloat162_rn(fq.z, fq.w);
    __nv_bfloat162 k0 = __floats2bfloat162_rn(fk.x, fk.y);
    __nv_bfloat162 k1 = __floats2bfloat162_rn(fk.z, fk.w);
    __nv_bfloat162 v0 = __floats2bfloat162_rn(fv.x, fv.y);
    __nv_bfloat162 v1 = __floats2bfloat162_rn(fv.z, fv.w);

    uint2 uq = { *(uint32_t*)&q0, *(uint32_t*)&q1 };
    uint2 uk = { *(uint32_t*)&k0, *(uint32_t*)&k1 };
    uint2 uv = { *(uint32_t*)&v0, *(uint32_t*)&v1 };
    *(uint2*)(g_q + o) = uq;
    *(uint2*)(g_k + o) = uk;
    *(uint2*)(g_v + o) = uv;
}

// ---------------- helpers ----------------
__device__ __forceinline__ unsigned su(const void* p) {
    return (unsigned)__cvta_generic_to_shared(p);
}
__device__ __forceinline__ void ldsm_x4(uint32_t r[4], unsigned addr) {
    asm volatile("ldmatrix.sync.aligned.m8n8.x4.shared.b16 {%0,%1,%2,%3}, [%4];"
                 : "=r"(r[0]), "=r"(r[1]), "=r"(r[2]), "=r"(r[3]) : "r"(addr));
}
__device__ __forceinline__ void ldsm_x4_t(uint32_t r[4], unsigned addr) {
    asm volatile("ldmatrix.sync.aligned.m8n8.x4.trans.shared.b16 {%0,%1,%2,%3}, [%4];"
                 : "=r"(r[0]), "=r"(r[1]), "=r"(r[2]), "=r"(r[3]) : "r"(addr));
}
__device__ __forceinline__ void mma16816(float c[4],
                                         uint32_t a0, uint32_t a1, uint32_t a2, uint32_t a3,
                                         uint32_t b0, uint32_t b1) {
    asm volatile(
        "mma.sync.aligned.m16n8k16.row.col.f32.bf16.bf16.f32 "
        "{%0,%1,%2,%3}, {%4,%5,%6,%7}, {%8,%9}, {%0,%1,%2,%3};"
        : "+f"(c[0]), "+f"(c[1]), "+f"(c[2]), "+f"(c[3])
        : "r"(a0), "r"(a1), "r"(a2), "r"(a3), "r"(b0), "r"(b1));
}
__device__ __forceinline__ float ex2f(float x) {
    float y; asm("ex2.approx.f32 %0, %1;" : "=f"(y) : "f"(x)); return y;
}
__device__ __forceinline__ uint32_t pack_bf2(float a, float b) {
    __nv_bfloat162 t = __floats2bfloat162_rn(a, b);
    return *reinterpret_cast<uint32_t*>(&t);
}
// round a pair f32 -> bf16 -> f32 with a single cvt
__device__ __forceinline__ void rb2(float a, float b, float& ra, float& rbv) {
    uint32_t u = pack_bf2(a, b);           // low = bf16(a), high = bf16(b)
    ra  = __uint_as_float(u << 16);
    rbv = __uint_as_float(u & 0xffff0000u);
}
__device__ __forceinline__ float rb(float x) {
    return __bfloat162float(__float2bfloat16(x));
}
__device__ __forceinline__ void cp_async16(void* smem, const void* gmem) {
    asm volatile("cp.async.cg.shared.global [%0], [%1], 16;\n"
                 :: "r"(su(smem)), "l"(gmem));
}
#define CP_COMMIT() asm volatile("cp.async.commit_group;\n" ::: "memory")
#define CP_WAIT0()  asm volatile("cp.async.wait_group 0;\n" ::: "memory")

// ---------------- flash attention, two-pass, max-free ex2 softmax ----------------
constexpr int SQ = 72;    // smem row stride (bf16); 144B = 16B-multiple, conflict-free
constexpr int QELEMS = 128 * SQ;
constexpr int TELEMS = 64 * SQ;
constexpr int SMEMB  = (QELEMS + 4 * TELEMS) * 2;   // 55296 bytes

// scale * log2(e): t = bf16(S) * C, p = 2^t
#define SCL2 0.18033688011112042f

__global__ __launch_bounds__(256, 2) void attn_kernel(float* __restrict__ out) {
    extern __shared__ __align__(16) __nv_bfloat16 smem[];
    __nv_bfloat16* sQ  = smem;
    __nv_bfloat16* sK0 = smem + QELEMS;
    __nv_bfloat16* sK1 = sK0 + TELEMS;
    __nv_bfloat16* sV0 = sK1 + TELEMS;
    __nv_bfloat16* sV1 = sV0 + TELEMS;
    __nv_bfloat16* sKb[2] = { sK0, sK1 };
    __nv_bfloat16* sVb[2] = { sV0, sV1 };

    const int tid  = threadIdx.x;
    const int warp = tid >> 5;
    const int lane = tid & 31;
    const int mblk = blockIdx.x;   // 0..15
    const int bh   = blockIdx.y;   // 0..63

    const __nv_bfloat16* Qg = g_q + (size_t)bh * Ndim * Ddim + (size_t)mblk * 128 * Ddim;
    const __nv_bfloat16* Kg = g_k + (size_t)bh * Ndim * Ddim;
    const __nv_bfloat16* Vg = g_v + (size_t)bh * Ndim * Ddim;

    // ---- stage Q tile + first K tile together ----
    {
        const char* src = (const char*)Qg;
        #pragma unroll
        for (int i = tid; i < 128 * 8; i += 256) {
            int row = i >> 3, c = i & 7;
            cp_async16(&sQ[row * SQ + c * 8], src + i * 16);
        }
        const char* srcK = (const char*)Kg;
        #pragma unroll
        for (int i = tid; i < 64 * 8; i += 256) {
            int row = i >> 3, c = i & 7;
            cp_async16(&sK0[row * SQ + c * 8], srcK + i * 16);
        }
        CP_COMMIT();
    }
    CP_WAIT0();
    __syncthreads();

    // ---- Q fragments, register resident ----
    uint32_t qa[4][4];
    {
        int rofs = warp * 16 + (lane & 15);
        int cofs = (lane & 16) ? 8 : 0;
        #pragma unroll
        for (int kk = 0; kk < 4; kk++)
            ldsm_x4(qa[kk], su(&sQ[rofs * SQ + kk * 16 + cofs]));
    }

    const int qgrp = lane >> 2;
    const int krow = lane & 7;
    const int kc8  = (lane >> 3) & 3;
    const int vrow = lane & 15;
    const int vcsel = (lane & 16) ? 8 : 0;

    // ===================== PASS 1: row denom l (max-free) =====================
    float l0 = 0.f, l1 = 0.f;

    for (int kt = 0; kt < 32; kt++) {
        if (kt > 0) { CP_WAIT0(); __syncthreads(); }
        if (kt + 1 < 32) {
            const char* srcK = (const char*)(Kg + (kt + 1) * 64 * Ddim);
            __nv_bfloat16* dst = sKb[(kt + 1) & 1];
            #pragma unroll
            for (int i = tid; i < 64 * 8; i += 256) {
                int row = i >> 3, c = i & 7;
                cp_async16(&dst[row * SQ + c * 8], srcK + i * 16);
            }
            CP_COMMIT();
        }
        const __nv_bfloat16* sK = sKb[kt & 1];

        float sc[8][4];
        #pragma unroll
        for (int nt = 0; nt < 8; nt++)
            #pragma unroll
            for (int x = 0; x < 4; x++) sc[nt][x] = 0.f;

        #pragma unroll
        for (int nt = 0; nt < 8; nt++) {
            #pragma unroll
            for (int kh = 0; kh < 2; kh++) {
                uint32_t kb[4];
                ldsm_x4(kb, su(&sK[(nt * 8 + krow) * SQ + kh * 32 + kc8 * 8]));
                mma16816(sc[nt], qa[2*kh][0], qa[2*kh][1], qa[2*kh][2], qa[2*kh][3], kb[0], kb[1]);
                mma16816(sc[nt], qa[2*kh+1][0], qa[2*kh+1][1], qa[2*kh+1][2], qa[2*kh+1][3], kb[2], kb[3]);
            }
        }

        float rs0 = 0.f, rs1 = 0.f;
        #pragma unroll
        for (int nt = 0; nt < 8; nt++) {
            float a0, a1, b0, b1;
            rb2(sc[nt][0], sc[nt][1], a0, a1);
            rb2(sc[nt][2], sc[nt][3], b0, b1);
            rs0 += ex2f(a0 * SCL2) + ex2f(a1 * SCL2);
            rs1 += ex2f(b0 * SCL2) + ex2f(b1 * SCL2);
        }
        l0 += rs0;
        l1 += rs1;
        if (kt + 1 == 32) __syncthreads();   // before pass-2 prefetch reuses buffers
    }
    l0 += __shfl_xor_sync(0xffffffffu, l0, 1);
    l0 += __shfl_xor_sync(0xffffffffu, l0, 2);
    l1 += __shfl_xor_sync(0xffffffffu, l1, 1);
    l1 += __shfl_xor_sync(0xffffffffu, l1, 2);
    const float invl0 = 1.0f / l0;
    const float invl1 = 1.0f / l1;

    // ===================== PASS 2: P = bf16(2^t / l), O = P V =====================
    float oa[8][4];
    #pragma unroll
    for (int u = 0; u < 8; u++)
        #pragma unroll
        for (int x = 0; x < 4; x++) oa[u][x] = 0.f;

    // prefetch tile 0 (K+V)
    {
        const char* srcK = (const char*)Kg;
        const char* srcV = (const char*)Vg;
        #pragma unroll
        for (int i = tid; i < 64 * 8; i += 256) {
            int row = i >> 3, c = i & 7;
            cp_async16(&sK0[row * SQ + c * 8], srcK + i * 16);
            cp_async16(&sV0[row * SQ + c * 8], srcV + i * 16);
        }
        CP_COMMIT();
    }

    for (int kt = 0; kt < 32; kt++) {
        CP_WAIT0();
        __syncthreads();
        if (kt + 1 < 32) {
            const char* srcK = (const char*)(Kg + (kt + 1) * 64 * Ddim);
            const char* srcV = (const char*)(Vg + (kt + 1) * 64 * Ddim);
            __nv_bfloat16* dK = sKb[(kt + 1) & 1];
            __nv_bfloat16* dV = sVb[(kt + 1) & 1];
            #pragma unroll
            for (int i = tid; i < 64 * 8; i += 256) {
                int row = i >> 3, c = i & 7;
                cp_async16(&dK[row * SQ + c * 8], srcK + i * 16);
                cp_async16(&dV[row * SQ + c * 8], srcV + i * 16);
            }
            CP_COMMIT();
        }
        const __nv_bfloat16* sK = sKb[kt & 1];
        const __nv_bfloat16* sV = sVb[kt & 1];

        float sc[8][4];
        #pragma unroll
        for (int nt = 0; nt < 8; nt++)
            #pragma unroll
            for (int x = 0; x < 4; x++) sc[nt][x] = 0.f;

        #pragma unroll
        for (int nt = 0; nt < 8; nt++) {
            #pragma unroll
            for (int kh = 0; kh < 2; kh++) {
                uint32_t kb[4];
                ldsm_x4(kb, su(&sK[(nt * 8 + krow) * SQ + kh * 32 + kc8 * 8]));
                mma16816(sc[nt], qa[2*kh][0], qa[2*kh][1], qa[2*kh][2], qa[2*kh][3], kb[0], kb[1]);
                mma16816(sc[nt], qa[2*kh+1][0], qa[2*kh+1][1], qa[2*kh+1][2], qa[2*kh+1][3], kb[2], kb[3]);
            }
        }

        uint32_t pA[8][2];
        #pragma unroll
        for (int nt = 0; nt < 8; nt++) {
            float a0, a1, b0, b1;
            rb2(sc[nt][0], sc[nt][1], a0, a1);
            rb2(sc[nt][2], sc[nt][3], b0, b1);
            float p00 = ex2f(a0 * SCL2) * invl0;
            float p01 = ex2f(a1 * SCL2) * invl0;
            float p10 = ex2f(b0 * SCL2) * invl1;
            float p11 = ex2f(b1 * SCL2) * invl1;
            pA[nt][0] = pack_bf2(p00, p01);
            pA[nt][1] = pack_bf2(p10, p11);
        }

        #pragma unroll
        for (int j = 0; j < 4; j++) {
            uint32_t A0 = pA[2*j][0], A1 = pA[2*j][1];
            uint32_t A2 = pA[2*j+1][0], A3 = pA[2*j+1][1];
            #pragma unroll
            for (int up = 0; up < 4; up++) {
                uint32_t vb[4];
                ldsm_x4_t(vb, su(&sV[(j * 16 + vrow) * SQ + up * 16 + vcsel]));
                mma16816(oa[2*up],     A0, A1, A2, A3, vb[0], vb[1]);
                mma16816(oa[2*up + 1], A0, A1, A2, A3, vb[2], vb[3]);
            }
        }
    }

    // ---- epilogue: bf16-round O, store as float32 in [B,N,H*D] ----
    int b = bh >> 4, h = bh & 15;
    int n0 = mblk * 128 + warp * 16 + qgrp;
    size_t base0 = ((size_t)b * Ndim + n0) * (Hdim * Ddim) + (size_t)h * Ddim;
    size_t base1 = base0 + (size_t)8 * (Hdim * Ddim);
    const int tq = lane & 3;
    #pragma unroll
    for (int u = 0; u < 8; u++) {
        int d = u * 8 + 2 * tq;
        float2 w0 = { rb(oa[u][0]), rb(oa[u][1]) };
        float2 w1 = { rb(oa[u][2]), rb(oa[u][3]) };
        *(float2*)(out + base0 + d) = w0;
        *(float2*)(out + base1 + d) = w1;
    }
}

// ---------------- launch ----------------
extern "C" void kernel_launch(void* const* d_in, const int* in_sizes, int n_in,
                              void* d_out, int out_size) {
    (void)in_sizes; (void)n_in; (void)out_size;
    const float* q = (const float*)d_in[0];
    const float* k = (const float*)d_in[1];
    const float* v = (const float*)d_in[2];
    float* out = (float*)d_out;

    cudaFuncSetAttribute(attn_kernel, cudaFuncAttributeMaxDynamicSharedMemorySize, SMEMB);

    cvt_kernel<<<TOTE / 1024, 256>>>(q, k, v);

    dim3 grid(Ndim / 128, Bdim * Hdim);
    attn_kernel<<<grid, 256, SMEMB>>>(out);
}

// round 5
// speedup vs baseline: 1.3401x; 1.0687x over previous
#include <cuda_runtime.h>
#include <cuda_bf16.h>
#include <cstdint>

#define Bdim 4
#define Hdim 16
#define Ndim 2048
#define Ddim 64
#define TOTE (Bdim*Hdim*Ndim*Ddim)   // 8388608

// bf16 scratch in [B, H, N, D] layout
__device__ __align__(16) __nv_bfloat16 g_q[TOTE];
__device__ __align__(16) __nv_bfloat16 g_k[TOTE];
__device__ __align__(16) __nv_bfloat16 g_v[TOTE];

// ---------------- converter: [B,N,H*D] f32 -> [B,H,N,D] bf16 ----------------
__global__ void cvt_kernel(const float* __restrict__ q,
                           const float* __restrict__ k,
                           const float* __restrict__ v) {
    long i4 = (long)blockIdx.x * blockDim.x + threadIdx.x;
    long o = i4 * 4;
    if (o >= TOTE) return;
    int d = (int)(o & 63);
    int n = (int)((o >> 6) & 2047);
    int h = (int)((o >> 17) & 15);
    int b = (int)(o >> 21);
    long in_off = (((long)b * Ndim + n) * Hdim + h) * Ddim + d;

    float4 fq = *(const float4*)(q + in_off);
    float4 fk = *(const float4*)(k + in_off);
    float4 fv = *(const float4*)(v + in_off);

    __nv_bfloat162 q0 = __floats2bfloat162_rn(fq.x, fq.y);
    __nv_bfloat162 q1 = __floats2bfloat162_rn(fq.z, fq.w);
    __nv_bfloat162 k0 = __floats2bfloat162_rn(fk.x, fk.y);
    __nv_bfloat162 k1 = __floats2bfloat162_rn(fk.z, fk.w);
    __nv_bfloat162 v0 = __floats2bfloat162_rn(fv.x, fv.y);
    __nv_bfloat162 v1 = __floats2bfloat162_rn(fv.z, fv.w);

    uint2 uq = { *(uint32_t*)&q0, *(uint32_t*)&q1 };
    uint2 uk = { *(uint32_t*)&k0, *(uint32_t*)&k1 };
    uint2 uv = { *(uint32_t*)&v0, *(uint32_t*)&v1 };
    *(uint2*)(g_q + o) = uq;
    *(uint2*)(g_k + o) = uk;
    *(uint2*)(g_v + o) = uv;
}

// ---------------- helpers ----------------
__device__ __forceinline__ unsigned su(const void* p) {
    return (unsigned)__cvta_generic_to_shared(p);
}
__device__ __forceinline__ void ldsm_x4(uint32_t r[4], unsigned addr) {
    asm volatile("ldmatrix.sync.aligned.m8n8.x4.shared.b16 {%0,%1,%2,%3}, [%4];"
                 : "=r"(r[0]), "=r"(r[1]), "=r"(r[2]), "=r"(r[3]) : "r"(addr));
}
__device__ __forceinline__ void ldsm_x4_t(uint32_t r[4], unsigned addr) {
    asm volatile("ldmatrix.sync.aligned.m8n8.x4.trans.shared.b16 {%0,%1,%2,%3}, [%4];"
                 : "=r"(r[0]), "=r"(r[1]), "=r"(r[2]), "=r"(r[3]) : "r"(addr));
}
__device__ __forceinline__ void mma16816(float c[4],
                                         uint32_t a0, uint32_t a1, uint32_t a2, uint32_t a3,
                                         uint32_t b0, uint32_t b1) {
    asm volatile(
        "mma.sync.aligned.m16n8k16.row.col.f32.bf16.bf16.f32 "
        "{%0,%1,%2,%3}, {%4,%5,%6,%7}, {%8,%9}, {%0,%1,%2,%3};"
        : "+f"(c[0]), "+f"(c[1]), "+f"(c[2]), "+f"(c[3])
        : "r"(a0), "r"(a1), "r"(a2), "r"(a3), "r"(b0), "r"(b1));
}
__device__ __forceinline__ float ex2f(float x) {
    float y; asm("ex2.approx.f32 %0, %1;" : "=f"(y) : "f"(x)); return y;
}
__device__ __forceinline__ uint32_t pack_bf2(float a, float b) {
    __nv_bfloat162 t = __floats2bfloat162_rn(a, b);
    return *reinterpret_cast<uint32_t*>(&t);
}
// round a pair f32 -> bf16 -> f32 with a single cvt
__device__ __forceinline__ void rb2(float a, float b, float& ra, float& rbv) {
    uint32_t u = pack_bf2(a, b);           // low = bf16(a), high = bf16(b)
    ra  = __uint_as_float(u << 16);
    rbv = __uint_as_float(u & 0xffff0000u);
}
__device__ __forceinline__ float rb(float x) {
    return __bfloat162float(__float2bfloat16(x));
}
__device__ __forceinline__ void cp_async16s(unsigned smem, const void* gmem) {
    asm volatile("cp.async.cg.shared.global [%0], [%1], 16;\n"
                 :: "r"(smem), "l"(gmem));
}
#define CP_COMMIT() asm volatile("cp.async.commit_group;\n" ::: "memory")
#define CP_WAIT0()  asm volatile("cp.async.wait_group 0;\n" ::: "memory")

// ---------------- flash attention, two-pass, max-free ex2 softmax ----------------
constexpr int SQ = 72;    // smem row stride (bf16); 144B, conflict-free for ldsm pattern
constexpr int QELEMS = 128 * SQ;
constexpr int TELEMS = 64 * SQ;
constexpr int SMEMB  = (QELEMS + 4 * TELEMS) * 2;   // 55296 bytes
constexpr int TBYTES = 64 * Ddim * 2;               // gmem bytes per K/V tile (8192)

// scale * log2(e): t = bf16(S) * C, p = 2^t
#define SCL2 0.18033688011112042f

__global__ __launch_bounds__(256, 2) void attn_kernel(float* __restrict__ out) {
    extern __shared__ __align__(16) __nv_bfloat16 smem[];
    __nv_bfloat16* sQ  = smem;
    __nv_bfloat16* sK0 = smem + QELEMS;
    __nv_bfloat16* sK1 = sK0 + TELEMS;
    __nv_bfloat16* sV0 = sK1 + TELEMS;
    __nv_bfloat16* sV1 = sV0 + TELEMS;

    const int tid  = threadIdx.x;
    const int warp = tid >> 5;
    const int lane = tid & 31;
    const int mblk = blockIdx.x;   // 0..15
    const int bh   = blockIdx.y;   // 0..63

    const __nv_bfloat16* Qg = g_q + (size_t)bh * Ndim * Ddim + (size_t)mblk * 128 * Ddim;
    const __nv_bfloat16* Kg = g_k + (size_t)bh * Ndim * Ddim;
    const __nv_bfloat16* Vg = g_v + (size_t)bh * Ndim * Ddim;

    // ---- hoisted shared-memory addresses (byte, shared space) ----
    const int krow = lane & 7;
    const int kc8  = (lane >> 3) & 3;
    const int vrow = lane & 15;
    const int vcsel = (lane & 16) ? 8 : 0;
    const unsigned kfragoff = (unsigned)((krow * SQ + kc8 * 8) * 2);
    const unsigned vfragoff = (unsigned)((vrow * SQ + vcsel) * 2);
    const unsigned kA[2] = { su(sK0) + kfragoff, su(sK1) + kfragoff };
    const unsigned vA[2] = { su(sV0) + vfragoff, su(sV1) + vfragoff };

    // cp.async staging: 512 vec16 per tile over 256 threads -> 2 per thread
    const int srow = tid >> 3, scol = tid & 7;
    const unsigned stoff0 = (unsigned)((srow * SQ + scol * 8) * 2);
    const unsigned stoff1 = stoff0 + (unsigned)(32 * SQ * 2);
    const unsigned dKs[2][2] = { { su(sK0) + stoff0, su(sK0) + stoff1 },
                                 { su(sK1) + stoff0, su(sK1) + stoff1 } };
    const unsigned dVs[2][2] = { { su(sV0) + stoff0, su(sV0) + stoff1 },
                                 { su(sV1) + stoff0, su(sV1) + stoff1 } };
    const char* gKt = (const char*)Kg + tid * 16;   // advances TBYTES per tile
    const char* gVt = (const char*)Vg + tid * 16;

    // ---- stage Q tile + first K tile ----
    {
        const char* src = (const char*)Qg;
        unsigned qdst = su(sQ) + stoff0;
        #pragma unroll
        for (int it = 0; it < 4; it++)   // 1024 vec16 / 256 threads
            cp_async16s(qdst + it * (unsigned)(32 * SQ * 2), src + tid * 16 + it * 4096);
        cp_async16s(dKs[0][0], gKt);
        cp_async16s(dKs[0][1], gKt + 4096);
        CP_COMMIT();
    }
    CP_WAIT0();
    __syncthreads();

    // ---- Q fragments, register resident ----
    uint32_t qa[4][4];
    {
        int rofs = warp * 16 + (lane & 15);
        int cofs = (lane & 16) ? 8 : 0;
        unsigned qaddr = su(sQ) + (unsigned)((rofs * SQ + cofs) * 2);
        #pragma unroll
        for (int kk = 0; kk < 4; kk++)
            ldsm_x4(qa[kk], qaddr + kk * 32);
    }

    const int qgrp = lane >> 2;

    // ===================== PASS 1: row denom l (max-free) =====================
    float l0 = 0.f, l1 = 0.f;

    {
        const char* gK = gKt + TBYTES;   // next tile to prefetch
        for (int kt = 0; kt < 32; kt++) {
            if (kt > 0) { CP_WAIT0(); __syncthreads(); }
            if (kt + 1 < 32) {
                const unsigned* d = dKs[(kt + 1) & 1];
                cp_async16s(d[0], gK);
                cp_async16s(d[1], gK + 4096);
                CP_COMMIT();
                gK += TBYTES;
            }
            const unsigned ka = kA[kt & 1];

            float sc[8][4];
            #pragma unroll
            for (int nt = 0; nt < 8; nt++)
                #pragma unroll
                for (int x = 0; x < 4; x++) sc[nt][x] = 0.f;

            #pragma unroll
            for (int nt = 0; nt < 8; nt++) {
                #pragma unroll
                for (int kh = 0; kh < 2; kh++) {
                    uint32_t kb[4];
                    ldsm_x4(kb, ka + (unsigned)(nt * 8 * SQ * 2 + kh * 64));
                    mma16816(sc[nt], qa[2*kh][0], qa[2*kh][1], qa[2*kh][2], qa[2*kh][3], kb[0], kb[1]);
                    mma16816(sc[nt], qa[2*kh+1][0], qa[2*kh+1][1], qa[2*kh+1][2], qa[2*kh+1][3], kb[2], kb[3]);
                }
            }

            float rs0 = 0.f, rs1 = 0.f;
            #pragma unroll
            for (int nt = 0; nt < 8; nt++) {
                float a0, a1, b0, b1;
                rb2(sc[nt][0], sc[nt][1], a0, a1);
                rb2(sc[nt][2], sc[nt][3], b0, b1);
                rs0 += ex2f(a0 * SCL2) + ex2f(a1 * SCL2);
                rs1 += ex2f(b0 * SCL2) + ex2f(b1 * SCL2);
            }
            l0 += rs0;
            l1 += rs1;
            if (kt + 1 == 32) __syncthreads();   // before pass-2 reuses buffers
        }
    }
    l0 += __shfl_xor_sync(0xffffffffu, l0, 1);
    l0 += __shfl_xor_sync(0xffffffffu, l0, 2);
    l1 += __shfl_xor_sync(0xffffffffu, l1, 1);
    l1 += __shfl_xor_sync(0xffffffffu, l1, 2);
    const float invl0 = 1.0f / l0;
    const float invl1 = 1.0f / l1;

    // ===================== PASS 2: P = bf16(2^t / l), O = P V =====================
    float oa[8][4];
    #pragma unroll
    for (int u = 0; u < 8; u++)
        #pragma unroll
        for (int x = 0; x < 4; x++) oa[u][x] = 0.f;

    // prefetch tile 0 (K+V)
    cp_async16s(dKs[0][0], gKt);
    cp_async16s(dKs[0][1], gKt + 4096);
    cp_async16s(dVs[0][0], gVt);
    cp_async16s(dVs[0][1], gVt + 4096);
    CP_COMMIT();
    gKt += TBYTES; gVt += TBYTES;

    for (int kt = 0; kt < 32; kt++) {
        CP_WAIT0();
        __syncthreads();
        if (kt + 1 < 32) {
            const unsigned* dK = dKs[(kt + 1) & 1];
            const unsigned* dV = dVs[(kt + 1) & 1];
            cp_async16s(dK[0], gKt);
            cp_async16s(dK[1], gKt + 4096);
            cp_async16s(dV[0], gVt);
            cp_async16s(dV[1], gVt + 4096);
            CP_COMMIT();
            gKt += TBYTES; gVt += TBYTES;
        }
        const unsigned ka = kA[kt & 1];
        const unsigned va = vA[kt & 1];

        float sc[8][4];
        #pragma unroll
        for (int nt = 0; nt < 8; nt++)
            #pragma unroll
            for (int x = 0; x < 4; x++) sc[nt][x] = 0.f;

        #pragma unroll
        for (int nt = 0; nt < 8; nt++) {
            #pragma unroll
            for (int kh = 0; kh < 2; kh++) {
                uint32_t kb[4];
                ldsm_x4(kb, ka + (unsigned)(nt * 8 * SQ * 2 + kh * 64));
                mma16816(sc[nt], qa[2*kh][0], qa[2*kh][1], qa[2*kh][2], qa[2*kh][3], kb[0], kb[1]);
                mma16816(sc[nt], qa[2*kh+1][0], qa[2*kh+1][1], qa[2*kh+1][2], qa[2*kh+1][3], kb[2], kb[3]);
            }
        }

        uint32_t pA[8][2];
        #pragma unroll
        for (int nt = 0; nt < 8; nt++) {
            float a0, a1, b0, b1;
            rb2(sc[nt][0], sc[nt][1], a0, a1);
            rb2(sc[nt][2], sc[nt][3], b0, b1);
            float p00 = ex2f(a0 * SCL2) * invl0;
            float p01 = ex2f(a1 * SCL2) * invl0;
            float p10 = ex2f(b0 * SCL2) * invl1;
            float p11 = ex2f(b1 * SCL2) * invl1;
            pA[nt][0] = pack_bf2(p00, p01);
            pA[nt][1] = pack_bf2(p10, p11);
        }

        #pragma unroll
        for (int j = 0; j < 4; j++) {
            uint32_t A0 = pA[2*j][0], A1 = pA[2*j][1];
            uint32_t A2 = pA[2*j+1][0], A3 = pA[2*j+1][1];
            #pragma unroll
            for (int up = 0; up < 4; up++) {
                uint32_t vb[4];
                ldsm_x4_t(vb, va + (unsigned)(j * 16 * SQ * 2 + up * 32));
                mma16816(oa[2*up],     A0, A1, A2, A3, vb[0], vb[1]);
                mma16816(oa[2*up + 1], A0, A1, A2, A3, vb[2], vb[3]);
            }
        }
    }

    // ---- epilogue: bf16-round O, store as float32 in [B,N,H*D] ----
    int b = bh >> 4, h = bh & 15;
    int n0 = mblk * 128 + warp * 16 + qgrp;
    size_t base0 = ((size_t)b * Ndim + n0) * (Hdim * Ddim) + (size_t)h * Ddim;
    size_t base1 = base0 + (size_t)8 * (Hdim * Ddim);
    const int tq = lane & 3;
    #pragma unroll
    for (int u = 0; u < 8; u++) {
        int d = u * 8 + 2 * tq;
        float2 w0 = { rb(oa[u][0]), rb(oa[u][1]) };
        float2 w1 = { rb(oa[u][2]), rb(oa[u][3]) };
        *(float2*)(out + base0 + d) = w0;
        *(float2*)(out + base1 + d) = w1;
    }
}

// ---------------- launch ----------------
extern "C" void kernel_launch(void* const* d_in, const int* in_sizes, int n_in,
                              void* d_out, int out_size) {
    (void)in_sizes; (void)n_in; (void)out_size;
    const float* q = (const float*)d_in[0];
    const float* k = (const float*)d_in[1];
    const float* v = (const float*)d_in[2];
    float* out = (float*)d_out;

    cudaFuncSetAttribute(attn_kernel, cudaFuncAttributeMaxDynamicSharedMemorySize, SMEMB);

    cvt_kernel<<<TOTE / 1024, 256>>>(q, k, v);

    dim3 grid(Ndim / 128, Bdim * Hdim);
    attn_kernel<<<grid, 256, SMEMB>>>(out);
}